// round 3
// baseline (speedup 1.0000x reference)
#include <cuda_runtime.h>

#define HOP 160
#define NFFT 512
#define NMEL 64
#define NFREQ 257
#define PREEMPH 0.97f
#define LOG_GUARD 5.9604644775390625e-8f   // 2^-24

#define MAXB 32
#define MAXT 1601
#define WPB 8    // warps (frames) per block

// ---- device scratch (no allocations allowed) ----
__device__ int    g_lo[NMEL], g_hi[NMEL];
__device__ float  g_mean[MAXB * NMEL];
__device__ float  g_rstd[MAXB * NMEL];
__device__ float  g_logmel[(size_t)MAXB * MAXT * NMEL];   // [b*T+t, m]

// twiddle tables (filled by init_kernel)
__device__ float  g_S_re[NFREQ], g_S_im[NFREQ];   // exp(-i*pi*f/256)
__device__ float  g_w1_re[32],  g_w1_im[32];      // exp(-2*pi*i*lane/256)
__device__ float  g_stw_re[5][32], g_stw_im[5][32]; // stage s (h=16>>s): exp(-i*pi*(lane&(h-1))/h)

// ---------------------------------------------------------------------------
__global__ void init_kernel(const float* __restrict__ fb) {
    int tid = threadIdx.x;
    if (tid < NFREQ) {
        float s, c;
        sincospif((float)tid / 256.0f, &s, &c);
        g_S_re[tid] = c;
        g_S_im[tid] = -s;
    }
    if (tid < 32) {
        float s, c;
        sincospif((float)tid / 128.0f, &s, &c);
        g_w1_re[tid] = c;
        g_w1_im[tid] = -s;
        #pragma unroll
        for (int st = 0; st < 5; st++) {
            int h = 16 >> st;
            int j = tid & (h - 1);
            float ss, cc;
            sincospif((float)j / (float)h, &ss, &cc);
            g_stw_re[st][tid] = cc;
            g_stw_im[st][tid] = -ss;
        }
    }
    if (tid >= 320 && tid < 320 + NMEL) {
        int m = tid - 320;
        int lo = NFREQ, hi = 0;
        const float* row = fb + m * NFREQ;
        for (int f = 0; f < NFREQ; f++) {
            if (row[f] != 0.0f) { if (f < lo) lo = f; hi = f; }
        }
        g_lo[m] = lo;
        g_hi[m] = hi;
    }
}

// ---------------------------------------------------------------------------
// frame kernel: ONE WARP per frame; register FFT; table twiddles (no sincospif)
// ---------------------------------------------------------------------------
__global__ __launch_bounds__(32 * WPB) void frame_kernel(
    const float* __restrict__ x, const float* __restrict__ win,
    const float* __restrict__ fb, int L, int T, int B)
{
    __shared__ float2 wsh[256];
    __shared__ float  sSr[NFREQ], sSi[NFREQ];
    __shared__ float  sW1r[32], sW1i[32];
    __shared__ float  sTr[5][32], sTi[5][32];
    __shared__ float  sh_re[WPB][288];   // idx + (idx>>3) padding
    __shared__ float  sh_im[WPB][288];
    __shared__ float  sh_pow[WPB][264];

    const int tid = threadIdx.x;
    const float2* win2 = (const float2*)win;
    for (int i = tid; i < 256; i += 32 * WPB) wsh[i] = win2[i];
    for (int i = tid; i < NFREQ; i += 32 * WPB) { sSr[i] = g_S_re[i]; sSi[i] = g_S_im[i]; }
    if (tid < 32) {
        sW1r[tid] = g_w1_re[tid];
        sW1i[tid] = g_w1_im[tid];
        #pragma unroll
        for (int st = 0; st < 5; st++) {
            sTr[st][tid] = g_stw_re[st][tid];
            sTi[st][tid] = g_stw_im[st][tid];
        }
    }
    __syncthreads();

    const int wid = tid >> 5;
    const int lane = tid & 31;
    const int fid = blockIdx.x * WPB + wid;
    if (fid >= B * T) return;
    const int b = fid / T;
    const int t = fid - b * T;
    const float* xb = x + (size_t)b * L;
    const int base = t * HOP - 256;

    // ---- pack: z[k] = y(2k) + i*y(2k+1), y = win * preemph(reflect(x)) ----
    float zr[8], zi[8];
    const bool fast = (t >= 2) && (t <= T - 3);   // uniform per warp
    #pragma unroll
    for (int p = 0; p < 8; p++) {
        int k = lane + 32 * p;
        float2 w2 = wsh[k];
        float vr = 0.0f, vi = 0.0f;
        if (w2.x != 0.0f || w2.y != 0.0f) {
            int n0 = base + 2 * k;
            if (fast) {
                float2 c = *(const float2*)(xb + n0);   // n0 even -> aligned
                float xm1 = xb[n0 - 1];
                vr = w2.x * (c.x - PREEMPH * xm1);
                vi = w2.y * (c.y - PREEMPH * c.x);
            } else {
                int q = n0 < 0 ? -n0 : n0;
                if (q >= L) q = 2 * (L - 1) - q;
                float y0 = (q == 0) ? xb[0] : (xb[q] - PREEMPH * xb[q - 1]);
                int n1 = n0 + 1;
                int q1 = n1 < 0 ? -n1 : n1;
                if (q1 >= L) q1 = 2 * (L - 1) - q1;
                float y1 = (q1 == 0) ? xb[0] : (xb[q1] - PREEMPH * xb[q1 - 1]);
                vr = w2.x * y0;
                vi = w2.y * y1;
            }
        }
        zr[p] = vr; zi[p] = vi;
    }

    // ---- per-lane DFT8 over p (DIF, constant twiddles) ----
    {
        const float C = 0.70710678118654752f;
        float tr[4], ti[4], ur[4], ui[4];
        #pragma unroll
        for (int p = 0; p < 4; p++) {
            tr[p] = zr[p] + zr[p + 4];  ti[p] = zi[p] + zi[p + 4];
            ur[p] = zr[p] - zr[p + 4];  ui[p] = zi[p] - zi[p + 4];
        }
        { float a = ur[1], bq = ui[1]; ur[1] = C * (a + bq); ui[1] = C * (bq - a); }
        { float a = ur[2], bq = ui[2]; ur[2] = bq; ui[2] = -a; }
        { float a = ur[3], bq = ui[3]; ur[3] = C * (bq - a); ui[3] = -C * (a + bq); }
        float ar = tr[0] + tr[2], ai = ti[0] + ti[2];
        float br = tr[0] - tr[2], bi = ti[0] - ti[2];
        float cr = tr[1] + tr[3], ci = ti[1] + ti[3];
        float dr = ti[1] - ti[3], di = -(tr[1] - tr[3]);
        zr[0] = ar + cr; zi[0] = ai + ci;
        zr[4] = ar - cr; zi[4] = ai - ci;
        zr[2] = br + dr; zi[2] = bi + di;
        zr[6] = br - dr; zi[6] = bi - di;
        ar = ur[0] + ur[2]; ai = ui[0] + ui[2];
        br = ur[0] - ur[2]; bi = ui[0] - ui[2];
        cr = ur[1] + ur[3]; ci = ui[1] + ui[3];
        dr = ui[1] - ui[3]; di = -(ur[1] - ur[3]);
        zr[1] = ar + cr; zi[1] = ai + ci;
        zr[5] = ar - cr; zi[5] = ai - ci;
        zr[3] = br + dr; zi[3] = bi + di;
        zr[7] = br - dr; zi[7] = bi - di;
    }

    // ---- per-lane twiddle chain (w1 from table) ----
    {
        float w1r = sW1r[lane], w1i = sW1i[lane];
        float wr = w1r, wi = w1i;
        #pragma unroll
        for (int k1 = 1; k1 < 8; k1++) {
            float nr = zr[k1] * wr - zi[k1] * wi;
            zi[k1]   = zr[k1] * wi + zi[k1] * wr;
            zr[k1]   = nr;
            float nwr = wr * w1r - wi * w1i;
            wi = wr * w1i + wi * w1r;
            wr = nwr;
        }
    }

    // ---- 32-pt cross-lane FFT (5 DIF radix-2 stages, shfl_xor) ----
    #pragma unroll
    for (int st = 0; st < 5; st++) {
        int h = 16 >> st;
        float c = sTr[st][lane];
        float ns = sTi[st][lane];                 // -sin
        bool up = (lane & h) != 0;
        #pragma unroll
        for (int k1 = 0; k1 < 8; k1++) {
            float pr = __shfl_xor_sync(0xFFFFFFFFu, zr[k1], h);
            float pi = __shfl_xor_sync(0xFFFFFFFFu, zi[k1], h);
            if (up) {
                float dr = pr - zr[k1], di = pi - zi[k1];
                zr[k1] = dr * c - di * ns;
                zi[k1] = di * c + dr * ns;
            } else {
                zr[k1] += pr;
                zi[k1] += pi;
            }
        }
    }
    // lane holds X[k1 + 8*bitrev5(lane)]

    // ---- store Z to padded shared (conflict-free) ----
    {
        int rev = __brev(lane) >> 27;
        int a0 = 9 * rev;
        #pragma unroll
        for (int k1 = 0; k1 < 8; k1++) {
            sh_re[wid][a0 + k1] = zr[k1];
            sh_im[wid][a0 + k1] = zi[k1];
        }
    }
    __syncwarp();

    // ---- real-FFT split + power spectrum (table twiddles) ----
    {
        #pragma unroll
        for (int r = 0; r < 8; r++) {
            int f = lane + 32 * r;
            int g = (256 - f) & 255;
            float zfr = sh_re[wid][f + (f >> 3)], zfi = sh_im[wid][f + (f >> 3)];
            float zgr = sh_re[wid][g + (g >> 3)], zgi = sh_im[wid][g + (g >> 3)];
            float er = 0.5f * (zfr + zgr);
            float ei = 0.5f * (zfi - zgi);
            float orr = 0.5f * (zfi + zgi);
            float oi  = -0.5f * (zfr - zgr);
            float wr = sSr[f], wi = sSi[f];
            float yr = er + wr * orr - wi * oi;
            float yi = ei + wr * oi + wi * orr;
            sh_pow[wid][f] = yr * yr + yi * yi;
        }
        if (lane == 0) {
            float d = sh_re[wid][0] - sh_im[wid][0];   // Y[256]
            sh_pow[wid][256] = d * d;
        }
    }
    __syncwarp();

    // ---- sparse mel projection + log (width-balanced: lane, 63-lane) ----
    {
        float* pw = sh_pow[wid];
        float* outp = g_logmel + (size_t)fid * NMEL;
        #pragma unroll
        for (int mm = 0; mm < 2; mm++) {
            int m = mm ? (63 - lane) : lane;
            int lo = g_lo[m], hi = g_hi[m];
            float acc = 0.0f;
            const float* frow = fb + m * NFREQ;
            int f = lo;
            for (; f + 3 <= hi; f += 4) {
                acc = fmaf(__ldg(frow + f),     pw[f],     acc);
                acc = fmaf(__ldg(frow + f + 1), pw[f + 1], acc);
                acc = fmaf(__ldg(frow + f + 2), pw[f + 2], acc);
                acc = fmaf(__ldg(frow + f + 3), pw[f + 3], acc);
            }
            for (; f <= hi; f++) acc = fmaf(__ldg(frow + f), pw[f], acc);
            outp[m] = __logf(acc + LOG_GUARD);
        }
    }
}

// ---------------------------------------------------------------------------
__global__ __launch_bounds__(1024) void stats_kernel(
    const int* __restrict__ seq_len, int T)
{
    __shared__ double sh_s[1024];
    __shared__ double sh_ss[1024];
    int b = blockIdx.x;
    int m = threadIdx.x & 63;
    int ph = threadIdx.x >> 6;      // 16 phases
    int flen = seq_len[b] / HOP + 1;

    float s = 0.0f, ss = 0.0f;
    for (int t = ph; t < flen; t += 16) {
        float v = g_logmel[((size_t)(b * T + t)) * NMEL + m];
        s += v;
        ss = fmaf(v, v, ss);
    }
    sh_s[threadIdx.x] = (double)s;
    sh_ss[threadIdx.x] = (double)ss;
    __syncthreads();
    if (ph == 0) {
        double ds = 0.0, dss = 0.0;
        #pragma unroll
        for (int i = 0; i < 16; i++) {
            ds += sh_s[m + 64 * i];
            dss += sh_ss[m + 64 * i];
        }
        double n = (double)flen;
        double mean = ds / n;
        double var = (dss - ds * ds / n) / (n - 1.0);
        if (var < 0.0) var = 0.0;
        double std = sqrt(var) + 1e-5;
        g_mean[b * NMEL + m] = (float)mean;
        g_rstd[b * NMEL + m] = (float)(1.0 / std);
    }
}

// ---------------------------------------------------------------------------
__global__ __launch_bounds__(256) void out_kernel(
    const int* __restrict__ seq_len, float* __restrict__ out,
    int T, int TP, int extra)
{
    __shared__ float tile[64 * 65];
    __shared__ float mu[64];
    __shared__ float rs[64];

    int b = blockIdx.y;
    int t0 = blockIdx.x * 64;
    int flen = seq_len[b] / HOP + 1;

    if (threadIdx.x < 64) {
        mu[threadIdx.x] = g_mean[b * NMEL + threadIdx.x];
        rs[threadIdx.x] = g_rstd[b * NMEL + threadIdx.x];
    }
    __syncthreads();

    #pragma unroll
    for (int r = 0; r < 16; r++) {
        int idx = r * 256 + threadIdx.x;
        int m = idx & 63;
        int tl = idx >> 6;
        int t = t0 + tl;
        float v = 0.0f;
        if (t < flen) {
            v = (g_logmel[((size_t)(b * T + t)) * NMEL + m] - mu[m]) * rs[m];
        }
        tile[tl * 65 + m] = v;
    }
    __syncthreads();

    #pragma unroll
    for (int r = 0; r < 16; r++) {
        int idx = r * 256 + threadIdx.x;
        int tl = idx & 63;
        int m = idx >> 6;
        int t = t0 + tl;
        if (t < TP) out[((size_t)b * NMEL + m) * TP + t] = tile[tl * 65 + m];
    }

    if (blockIdx.x == 0 && threadIdx.x == 0 && b < extra) {
        size_t tail = (size_t)gridDim.y * NMEL * TP;
        out[tail + b] = (float)flen;
    }
}

// ---------------------------------------------------------------------------
extern "C" void kernel_launch(void* const* d_in, const int* in_sizes, int n_in,
                              void* d_out, int out_size)
{
    const float* x   = (const float*)d_in[0];
    const int*   seq = (const int*)d_in[1];
    const float* win = (const float*)d_in[2];
    const float* fb  = (const float*)d_in[3];
    float* out = (float*)d_out;

    int B = in_sizes[1];
    int L = in_sizes[0] / B;
    int T = L / HOP + 1;
    int TP = ((T + 15) / 16) * 16;

    init_kernel<<<1, 512>>>(fb);

    int nframes = B * T;
    int nblocks = (nframes + WPB - 1) / WPB;
    frame_kernel<<<nblocks, 32 * WPB>>>(x, win, fb, L, T, B);

    stats_kernel<<<B, 1024>>>(seq, T);

    int nchunk = (TP + 63) / 64;
    long long extra = (long long)out_size - (long long)B * NMEL * TP;
    int ex = extra > 0 ? (int)(extra < B ? extra : B) : 0;
    out_kernel<<<dim3(nchunk, B), 256>>>(seq, out, T, TP, ex);
}

// round 4
// speedup vs baseline: 1.0996x; 1.0996x over previous
#include <cuda_runtime.h>

#define HOP 160
#define NFFT 512
#define NMEL 64
#define NFREQ 257
#define PREEMPH 0.97f
#define LOG_GUARD 5.9604644775390625e-8f   // 2^-24

#define MAXB 32
#define MAXT 1601
#define WPB 8                      // frames (warps) per block
#define SEG (HOP * (WPB - 1) + NFFT)   // 1632 staged samples per block

// ---- device scratch (no allocations allowed) ----
__device__ int    g_lo[NMEL], g_hi[NMEL];
__device__ float  g_mean[MAXB * NMEL];
__device__ float  g_rstd[MAXB * NMEL];
__device__ float  g_logmel[(size_t)MAXB * MAXT * NMEL];   // [b*T+t, m]

// ---------------------------------------------------------------------------
// init: mel filter support ranges (filters are triangular -> contiguous)
// ---------------------------------------------------------------------------
__global__ void init_kernel(const float* __restrict__ fb) {
    int m = threadIdx.x;
    if (m < NMEL) {
        int lo = NFREQ, hi = 0;
        const float* row = fb + m * NFREQ;
        for (int f = 0; f < NFREQ; f++) {
            if (row[f] != 0.0f) { if (f < lo) lo = f; hi = f; }
        }
        g_lo[m] = lo;
        g_hi[m] = hi;
    }
}

// ---------------------------------------------------------------------------
// frame kernel: block = 8 consecutive frames of one batch row.
// Stage 1632 preemph'd samples to shared (coalesced), then one warp per frame
// does a 256-pt register FFT (DFT8 x 32-lane shfl FFT), real split, sparse mel.
// ---------------------------------------------------------------------------
__global__ __launch_bounds__(32 * WPB) void frame_kernel(
    const float* __restrict__ x, const float* __restrict__ win,
    const float* __restrict__ fb, int L, int T, int nchunk)
{
    __shared__ float  sy[SEG];           // preemph'd, reflect-resolved samples
    __shared__ float2 wsh[256];
    __shared__ float  sh_re[WPB][288];   // idx + (idx>>3) padding
    __shared__ float  sh_im[WPB][288];
    __shared__ float  sh_pow[WPB][264];

    const int tid = threadIdx.x;
    const int b = blockIdx.x / nchunk;
    const int chunk = blockIdx.x - b * nchunk;
    const int t0 = chunk * WPB;
    const float* xb = x + (size_t)b * L;
    const int base0 = t0 * HOP - (NFFT / 2);

    // ---- window to shared ----
    const float2* win2 = (const float2*)win;
    for (int i = tid; i < 256; i += 32 * WPB) wsh[i] = win2[i];

    // ---- stage input segment: y[n] = preemph(x)[reflect(n)] ----
    if (base0 >= 1 && base0 + SEG <= L) {
        // fast path: no reflection anywhere in the segment
        #pragma unroll
        for (int r = 0; r < 7; r++) {
            int i = tid + r * 256;
            if (i < SEG) {
                int n = base0 + i;
                sy[i] = xb[n] - PREEMPH * xb[n - 1];
            }
        }
    } else {
        #pragma unroll
        for (int r = 0; r < 7; r++) {
            int i = tid + r * 256;
            if (i < SEG) {
                int n = base0 + i;
                int q = n < 0 ? -n : n;
                if (q >= L) q = 2 * (L - 1) - q;
                sy[i] = (q == 0) ? xb[0] : (xb[q] - PREEMPH * xb[q - 1]);
            }
        }
    }
    __syncthreads();

    const int wid = tid >> 5;
    const int lane = tid & 31;
    const int t = t0 + wid;
    if (t >= T) return;
    const int fid = b * T + t;

    // ---- pack from shared: z[k] = y(2k) + i*y(2k+1), windowed ----
    float zr[8], zi[8];
    const float2* sy2 = (const float2*)sy;
    const int sb = 80 * wid;             // (160*wid)/2 float2 offset
    #pragma unroll
    for (int p = 0; p < 8; p++) {
        int k = lane + 32 * p;
        float2 w2 = wsh[k];
        float2 v = sy2[sb + k];
        zr[p] = w2.x * v.x;
        zi[p] = w2.y * v.y;
    }

    // ---- per-lane DFT8 over p (DIF, constant twiddles) ----
    {
        const float C = 0.70710678118654752f;
        float tr[4], ti[4], ur[4], ui[4];
        #pragma unroll
        for (int p = 0; p < 4; p++) {
            tr[p] = zr[p] + zr[p + 4];  ti[p] = zi[p] + zi[p + 4];
            ur[p] = zr[p] - zr[p + 4];  ui[p] = zi[p] - zi[p + 4];
        }
        { float a = ur[1], bq = ui[1]; ur[1] = C * (a + bq); ui[1] = C * (bq - a); }
        { float a = ur[2], bq = ui[2]; ur[2] = bq; ui[2] = -a; }
        { float a = ur[3], bq = ui[3]; ur[3] = C * (bq - a); ui[3] = -C * (a + bq); }
        float ar = tr[0] + tr[2], ai = ti[0] + ti[2];
        float br = tr[0] - tr[2], bi = ti[0] - ti[2];
        float cr = tr[1] + tr[3], ci = ti[1] + ti[3];
        float dr = ti[1] - ti[3], di = -(tr[1] - tr[3]);
        zr[0] = ar + cr; zi[0] = ai + ci;
        zr[4] = ar - cr; zi[4] = ai - ci;
        zr[2] = br + dr; zi[2] = bi + di;
        zr[6] = br - dr; zi[6] = bi - di;
        ar = ur[0] + ur[2]; ai = ui[0] + ui[2];
        br = ur[0] - ur[2]; bi = ui[0] - ui[2];
        cr = ur[1] + ur[3]; ci = ui[1] + ui[3];
        dr = ui[1] - ui[3]; di = -(ur[1] - ur[3]);
        zr[1] = ar + cr; zi[1] = ai + ci;
        zr[5] = ar - cr; zi[5] = ai - ci;
        zr[3] = br + dr; zi[3] = bi + di;
        zr[7] = br - dr; zi[7] = bi - di;
    }

    // ---- per-lane twiddle: A[k1] *= exp(-2*pi*i*lane*k1/256) via chain ----
    {
        float s1, c1;
        sincospif((float)lane / 128.0f, &s1, &c1);
        float w1r = c1, w1i = -s1;
        float wr = w1r, wi = w1i;
        #pragma unroll
        for (int k1 = 1; k1 < 8; k1++) {
            float nr = zr[k1] * wr - zi[k1] * wi;
            zi[k1]   = zr[k1] * wi + zi[k1] * wr;
            zr[k1]   = nr;
            float nwr = wr * w1r - wi * w1i;
            wi = wr * w1i + wi * w1r;
            wr = nwr;
        }
    }

    // ---- 32-pt cross-lane FFT (5 DIF radix-2 stages, shfl_xor) ----
    #pragma unroll
    for (int h = 16; h >= 1; h >>= 1) {
        int j = lane & (h - 1);
        float s, c;
        sincospif((float)j / (float)h, &s, &c);      // w = (c, -s)
        bool up = (lane & h) != 0;
        #pragma unroll
        for (int k1 = 0; k1 < 8; k1++) {
            float pr = __shfl_xor_sync(0xFFFFFFFFu, zr[k1], h);
            float pi = __shfl_xor_sync(0xFFFFFFFFu, zi[k1], h);
            if (up) {
                float dr = pr - zr[k1], di = pi - zi[k1];
                zr[k1] = dr * c + di * s;
                zi[k1] = di * c - dr * s;
            } else {
                zr[k1] += pr;
                zi[k1] += pi;
            }
        }
    }
    // lane holds X[k1 + 8*bitrev5(lane)]

    // ---- store Z to padded shared (conflict-free: 9*rev is odd-stride) ----
    {
        int rev = __brev(lane) >> 27;
        int a0 = 9 * rev;
        #pragma unroll
        for (int k1 = 0; k1 < 8; k1++) {
            sh_re[wid][a0 + k1] = zr[k1];
            sh_im[wid][a0 + k1] = zi[k1];
        }
    }
    __syncwarp();

    // ---- real-FFT split + power spectrum ----
    {
        float bs, bc;
        sincospif((float)lane / 256.0f, &bs, &bc);
        float wr = bc, wi = -bs;                       // exp(-i*pi*f/256), f=lane
        const float STC = 0.92387953251128674f;        // cos(pi/8)
        const float STS = -0.38268343236508977f;       // -sin(pi/8)
        #pragma unroll
        for (int r = 0; r < 8; r++) {
            int f = lane + 32 * r;
            int g = (256 - f) & 255;
            float zfr = sh_re[wid][f + (f >> 3)], zfi = sh_im[wid][f + (f >> 3)];
            float zgr = sh_re[wid][g + (g >> 3)], zgi = sh_im[wid][g + (g >> 3)];
            float er = 0.5f * (zfr + zgr);
            float ei = 0.5f * (zfi - zgi);
            float orr = 0.5f * (zfi + zgi);
            float oi  = -0.5f * (zfr - zgr);
            float yr = er + wr * orr - wi * oi;
            float yi = ei + wr * oi + wi * orr;
            sh_pow[wid][f] = yr * yr + yi * yi;
            float nr = wr * STC - wi * STS;
            wi = wr * STS + wi * STC;
            wr = nr;
        }
        if (lane == 0) {
            float d = sh_re[wid][0] - sh_im[wid][0];   // Y[256]
            sh_pow[wid][256] = d * d;
        }
    }
    __syncwarp();

    // ---- sparse mel projection + log (width-balanced: lane, 63-lane) ----
    {
        float* pw = sh_pow[wid];
        float* outp = g_logmel + (size_t)fid * NMEL;
        #pragma unroll
        for (int mm = 0; mm < 2; mm++) {
            int m = mm ? (63 - lane) : lane;
            int lo = g_lo[m], hi = g_hi[m];
            float acc = 0.0f;
            const float* frow = fb + m * NFREQ;
            int f = lo;
            for (; f + 3 <= hi; f += 4) {
                acc = fmaf(__ldg(frow + f),     pw[f],     acc);
                acc = fmaf(__ldg(frow + f + 1), pw[f + 1], acc);
                acc = fmaf(__ldg(frow + f + 2), pw[f + 2], acc);
                acc = fmaf(__ldg(frow + f + 3), pw[f + 3], acc);
            }
            for (; f <= hi; f++) acc = fmaf(__ldg(frow + f), pw[f], acc);
            outp[m] = __logf(acc + LOG_GUARD);
        }
    }
}

// ---------------------------------------------------------------------------
// stats: masked mean / unbiased std per (b, m)
// ---------------------------------------------------------------------------
__global__ __launch_bounds__(1024) void stats_kernel(
    const int* __restrict__ seq_len, int T)
{
    __shared__ double sh_s[1024];
    __shared__ double sh_ss[1024];
    int b = blockIdx.x;
    int m = threadIdx.x & 63;
    int ph = threadIdx.x >> 6;      // 16 phases
    int flen = seq_len[b] / HOP + 1;

    float s = 0.0f, ss = 0.0f;
    for (int t = ph; t < flen; t += 16) {
        float v = g_logmel[((size_t)(b * T + t)) * NMEL + m];
        s += v;
        ss = fmaf(v, v, ss);
    }
    sh_s[threadIdx.x] = (double)s;
    sh_ss[threadIdx.x] = (double)ss;
    __syncthreads();
    if (ph == 0) {
        double ds = 0.0, dss = 0.0;
        #pragma unroll
        for (int i = 0; i < 16; i++) {
            ds += sh_s[m + 64 * i];
            dss += sh_ss[m + 64 * i];
        }
        double n = (double)flen;
        double mean = ds / n;
        double var = (dss - ds * ds / n) / (n - 1.0);
        if (var < 0.0) var = 0.0;
        double std = sqrt(var) + 1e-5;
        g_mean[b * NMEL + m] = (float)mean;
        g_rstd[b * NMEL + m] = (float)(1.0 / std);
    }
}

// ---------------------------------------------------------------------------
// normalize + transpose [b,t,m] -> [b,m,t], zero masked/pad frames,
// optional feat_len tail
// ---------------------------------------------------------------------------
__global__ __launch_bounds__(256) void out_kernel(
    const int* __restrict__ seq_len, float* __restrict__ out,
    int T, int TP, int extra)
{
    __shared__ float tile[64 * 65];
    __shared__ float mu[64];
    __shared__ float rs[64];

    int b = blockIdx.y;
    int t0 = blockIdx.x * 64;
    int flen = seq_len[b] / HOP + 1;

    if (threadIdx.x < 64) {
        mu[threadIdx.x] = g_mean[b * NMEL + threadIdx.x];
        rs[threadIdx.x] = g_rstd[b * NMEL + threadIdx.x];
    }
    __syncthreads();

    #pragma unroll
    for (int r = 0; r < 16; r++) {
        int idx = r * 256 + threadIdx.x;
        int m = idx & 63;
        int tl = idx >> 6;
        int t = t0 + tl;
        float v = 0.0f;
        if (t < flen) {
            v = (g_logmel[((size_t)(b * T + t)) * NMEL + m] - mu[m]) * rs[m];
        }
        tile[tl * 65 + m] = v;
    }
    __syncthreads();

    #pragma unroll
    for (int r = 0; r < 16; r++) {
        int idx = r * 256 + threadIdx.x;
        int tl = idx & 63;
        int m = idx >> 6;
        int t = t0 + tl;
        if (t < TP) out[((size_t)b * NMEL + m) * TP + t] = tile[tl * 65 + m];
    }

    if (blockIdx.x == 0 && threadIdx.x == 0 && b < extra) {
        size_t tail = (size_t)gridDim.y * NMEL * TP;
        out[tail + b] = (float)flen;
    }
}

// ---------------------------------------------------------------------------
extern "C" void kernel_launch(void* const* d_in, const int* in_sizes, int n_in,
                              void* d_out, int out_size)
{
    const float* x   = (const float*)d_in[0];
    const int*   seq = (const int*)d_in[1];
    const float* win = (const float*)d_in[2];
    const float* fb  = (const float*)d_in[3];
    float* out = (float*)d_out;

    int B = in_sizes[1];
    int L = in_sizes[0] / B;
    int T = L / HOP + 1;
    int TP = ((T + 15) / 16) * 16;

    init_kernel<<<1, 64>>>(fb);

    int nchunk_f = (T + WPB - 1) / WPB;
    frame_kernel<<<B * nchunk_f, 32 * WPB>>>(x, win, fb, L, T, nchunk_f);

    stats_kernel<<<B, 1024>>>(seq, T);

    int nchunk = (TP + 63) / 64;
    long long extra = (long long)out_size - (long long)B * NMEL * TP;
    int ex = extra > 0 ? (int)(extra < B ? extra : B) : 0;
    out_kernel<<<dim3(nchunk, B), 256>>>(seq, out, T, TP, ex);
}

// round 5
// speedup vs baseline: 1.1874x; 1.0798x over previous
#include <cuda_runtime.h>

#define HOP 160
#define NFFT 512
#define NMEL 64
#define NFREQ 257
#define PREEMPH 0.97f
#define LOG_GUARD 5.9604644775390625e-8f   // 2^-24

#define MAXB 32
#define MAXT 1601
#define WPB 8                      // frames (warps) per block
#define SEG (HOP * (WPB - 1) + NFFT)   // 1632 staged samples per block

// ---- device scratch (no allocations allowed) ----
__device__ int    g_lo[NMEL], g_hi[NMEL];
__device__ float  g_mean[MAXB * NMEL];
__device__ float  g_rstd[MAXB * NMEL];
__device__ float  g_logmel[(size_t)MAXB * MAXT * NMEL];   // [b*T+t, m]

// ---------------------------------------------------------------------------
__global__ void init_kernel(const float* __restrict__ fb) {
    int m = threadIdx.x;
    if (m < NMEL) {
        int lo = NFREQ, hi = 0;
        const float* row = fb + m * NFREQ;
        for (int f = 0; f < NFREQ; f++) {
            if (row[f] != 0.0f) { if (f < lo) lo = f; hi = f; }
        }
        g_lo[m] = lo;
        g_hi[m] = hi;
    }
}

// ---------------------------------------------------------------------------
// frame kernel: block = 8 consecutive frames of one batch row.
// Stage preemph'd samples to shared once; one warp per frame does a 256-pt
// register FFT (DFT8 x 32-lane shfl FFT), paired real split, sparse mel.
// ---------------------------------------------------------------------------
__global__ __launch_bounds__(32 * WPB) void frame_kernel(
    const float* __restrict__ x, const float* __restrict__ win,
    const float* __restrict__ fb, int L, int T, int nchunk)
{
    __shared__ float  sy[SEG];
    __shared__ float2 wsh[256];
    __shared__ float  sh_re[WPB][288];   // idx + (idx>>3) padding
    __shared__ float  sh_im[WPB][288];
    __shared__ float  sh_pow[WPB][264];

    const int tid = threadIdx.x;
    const int b = blockIdx.x / nchunk;
    const int chunk = blockIdx.x - b * nchunk;
    const int t0 = chunk * WPB;
    const float* xb = x + (size_t)b * L;
    const int base0 = t0 * HOP - (NFFT / 2);

    const float2* win2 = (const float2*)win;
    for (int i = tid; i < 256; i += 32 * WPB) wsh[i] = win2[i];

    // ---- stage input segment: y[n] = preemph(x)[reflect(n)] ----
    if (base0 >= 1 && base0 + SEG <= L) {
        #pragma unroll
        for (int r = 0; r < 7; r++) {
            int i = tid + r * 256;
            if (i < SEG) {
                int n = base0 + i;
                sy[i] = xb[n] - PREEMPH * xb[n - 1];
            }
        }
    } else {
        #pragma unroll
        for (int r = 0; r < 7; r++) {
            int i = tid + r * 256;
            if (i < SEG) {
                int n = base0 + i;
                int q = n < 0 ? -n : n;
                if (q >= L) q = 2 * (L - 1) - q;
                sy[i] = (q == 0) ? xb[0] : (xb[q] - PREEMPH * xb[q - 1]);
            }
        }
    }
    __syncthreads();

    const int wid = tid >> 5;
    const int lane = tid & 31;
    const int t = t0 + wid;
    if (t >= T) return;
    const int fid = b * T + t;

    // ---- pack from shared: z[k] = y(2k) + i*y(2k+1), windowed ----
    float zr[8], zi[8];
    const float2* sy2 = (const float2*)sy;
    const int sb = 80 * wid;
    #pragma unroll
    for (int p = 0; p < 8; p++) {
        int k = lane + 32 * p;
        float2 w2 = wsh[k];
        float2 v = sy2[sb + k];
        zr[p] = w2.x * v.x;
        zi[p] = w2.y * v.y;
    }

    // ---- per-lane DFT8 over p (DIF, constant twiddles) ----
    {
        const float C = 0.70710678118654752f;
        float tr[4], ti[4], ur[4], ui[4];
        #pragma unroll
        for (int p = 0; p < 4; p++) {
            tr[p] = zr[p] + zr[p + 4];  ti[p] = zi[p] + zi[p + 4];
            ur[p] = zr[p] - zr[p + 4];  ui[p] = zi[p] - zi[p + 4];
        }
        { float a = ur[1], bq = ui[1]; ur[1] = C * (a + bq); ui[1] = C * (bq - a); }
        { float a = ur[2], bq = ui[2]; ur[2] = bq; ui[2] = -a; }
        { float a = ur[3], bq = ui[3]; ur[3] = C * (bq - a); ui[3] = -C * (a + bq); }
        float ar = tr[0] + tr[2], ai = ti[0] + ti[2];
        float br = tr[0] - tr[2], bi = ti[0] - ti[2];
        float cr = tr[1] + tr[3], ci = ti[1] + ti[3];
        float dr = ti[1] - ti[3], di = -(tr[1] - tr[3]);
        zr[0] = ar + cr; zi[0] = ai + ci;
        zr[4] = ar - cr; zi[4] = ai - ci;
        zr[2] = br + dr; zi[2] = bi + di;
        zr[6] = br - dr; zi[6] = bi - di;
        ar = ur[0] + ur[2]; ai = ui[0] + ui[2];
        br = ur[0] - ur[2]; bi = ui[0] - ui[2];
        cr = ur[1] + ur[3]; ci = ui[1] + ui[3];
        dr = ui[1] - ui[3]; di = -(ur[1] - ur[3]);
        zr[1] = ar + cr; zi[1] = ai + ci;
        zr[5] = ar - cr; zi[5] = ai - ci;
        zr[3] = br + dr; zi[3] = bi + di;
        zr[7] = br - dr; zi[7] = bi - di;
    }

    // ---- per-lane twiddle: A[k1] *= exp(-2*pi*i*lane*k1/256) via chain ----
    {
        float s1, c1;
        sincospif((float)lane / 128.0f, &s1, &c1);
        float w1r = c1, w1i = -s1;
        float wr = w1r, wi = w1i;
        #pragma unroll
        for (int k1 = 1; k1 < 8; k1++) {
            float nr = zr[k1] * wr - zi[k1] * wi;
            zi[k1]   = zr[k1] * wi + zi[k1] * wr;
            zr[k1]   = nr;
            float nwr = wr * w1r - wi * w1i;
            wi = wr * w1i + wi * w1r;
            wr = nwr;
        }
    }

    // ---- 32-pt cross-lane FFT: unified branch-free butterflies ----
    // stages h = 16, 8, 4, 2 with twiddle (w=1 on down lanes); h=1 twiddle-free
    #pragma unroll
    for (int st = 0; st < 4; st++) {
        int h = 16 >> st;
        bool up = (lane & h) != 0;
        float sg = up ? -1.0f : 1.0f;
        int j = lane & (h - 1);
        float ss, cc;
        sincospif((float)j / (float)h, &ss, &cc);
        float wr = up ? cc : 1.0f;
        float wi = up ? -ss : 0.0f;
        #pragma unroll
        for (int k1 = 0; k1 < 8; k1++) {
            float pr = __shfl_xor_sync(0xFFFFFFFFu, zr[k1], h);
            float pi = __shfl_xor_sync(0xFFFFFFFFu, zi[k1], h);
            float dr = fmaf(sg, zr[k1], pr);
            float di = fmaf(sg, zi[k1], pi);
            zr[k1] = dr * wr - di * wi;
            zi[k1] = dr * wi + di * wr;
        }
    }
    {   // h = 1: twiddle is identity
        float sg = (lane & 1) ? -1.0f : 1.0f;
        #pragma unroll
        for (int k1 = 0; k1 < 8; k1++) {
            float pr = __shfl_xor_sync(0xFFFFFFFFu, zr[k1], 1);
            float pi = __shfl_xor_sync(0xFFFFFFFFu, zi[k1], 1);
            zr[k1] = fmaf(sg, zr[k1], pr);
            zi[k1] = fmaf(sg, zi[k1], pi);
        }
    }
    // lane holds X[k1 + 8*bitrev5(lane)]

    // ---- store Z to padded shared (conflict-free: 9*rev is odd-stride) ----
    {
        int rev = __brev(lane) >> 27;
        int a0 = 9 * rev;
        #pragma unroll
        for (int k1 = 0; k1 < 8; k1++) {
            sh_re[wid][a0 + k1] = zr[k1];
            sh_im[wid][a0 + k1] = zi[k1];
        }
    }
    __syncwarp();

    // ---- paired real-FFT split + power spectrum ----
    // Y_f = E + W O ; Y_{256-f} = conj(E - W O)  ->  one W·O serves two bins
    {
        float bs, bc;
        sincospif((float)lane / 256.0f, &bs, &bc);
        float wr = bc, wi = -bs;                       // exp(-i*pi*f/256), f=lane
        const float STC = 0.92387953251128674f;        // cos(pi/8)
        const float STS = -0.38268343236508977f;       // -sin(pi/8)
        #pragma unroll
        for (int r = 0; r < 4; r++) {
            int f = lane + 32 * r;                     // 0..127
            int g = 256 - f;                           // 129..256
            float zfr = sh_re[wid][f + (f >> 3)], zfi = sh_im[wid][f + (f >> 3)];
            float zgr = sh_re[wid][g + (g >> 3)], zgi = sh_im[wid][g + (g >> 3)];
            float er = 0.5f * (zfr + zgr);
            float ei = 0.5f * (zfi - zgi);
            float orr = 0.5f * (zfi + zgi);
            float oi  = -0.5f * (zfr - zgr);
            float ur = wr * orr - wi * oi;
            float ui = wr * oi + wi * orr;
            float ar = er + ur, ai = ei + ui;
            float br = er - ur, bi = ei - ui;
            sh_pow[wid][f] = fmaf(ar, ar, ai * ai);
            sh_pow[wid][g] = fmaf(br, br, bi * bi);
            float nr = wr * STC - wi * STS;
            wi = wr * STS + wi * STC;
            wr = nr;
        }
        if (lane == 0) {
            float hr = sh_re[wid][144], hi = sh_im[wid][144];  // Z[128] (padded)
            sh_pow[wid][128] = fmaf(hr, hr, hi * hi);
        }
    }
    __syncwarp();

    // ---- sparse mel projection + log (width-balanced: lane, 63-lane) ----
    {
        float* pw = sh_pow[wid];
        float* outp = g_logmel + (size_t)fid * NMEL;
        #pragma unroll
        for (int mm = 0; mm < 2; mm++) {
            int m = mm ? (63 - lane) : lane;
            int lo = g_lo[m], hi = g_hi[m];
            float acc = 0.0f;
            const float* frow = fb + m * NFREQ;
            int f = lo;
            for (; f + 3 <= hi; f += 4) {
                acc = fmaf(__ldg(frow + f),     pw[f],     acc);
                acc = fmaf(__ldg(frow + f + 1), pw[f + 1], acc);
                acc = fmaf(__ldg(frow + f + 2), pw[f + 2], acc);
                acc = fmaf(__ldg(frow + f + 3), pw[f + 3], acc);
            }
            for (; f <= hi; f++) acc = fmaf(__ldg(frow + f), pw[f], acc);
            outp[m] = __logf(acc + LOG_GUARD);
        }
    }
}

// ---------------------------------------------------------------------------
__global__ __launch_bounds__(1024) void stats_kernel(
    const int* __restrict__ seq_len, int T)
{
    __shared__ double sh_s[1024];
    __shared__ double sh_ss[1024];
    int b = blockIdx.x;
    int m = threadIdx.x & 63;
    int ph = threadIdx.x >> 6;      // 16 phases
    int flen = seq_len[b] / HOP + 1;

    float s = 0.0f, ss = 0.0f;
    for (int t = ph; t < flen; t += 16) {
        float v = g_logmel[((size_t)(b * T + t)) * NMEL + m];
        s += v;
        ss = fmaf(v, v, ss);
    }
    sh_s[threadIdx.x] = (double)s;
    sh_ss[threadIdx.x] = (double)ss;
    __syncthreads();
    if (ph == 0) {
        double ds = 0.0, dss = 0.0;
        #pragma unroll
        for (int i = 0; i < 16; i++) {
            ds += sh_s[m + 64 * i];
            dss += sh_ss[m + 64 * i];
        }
        double n = (double)flen;
        double mean = ds / n;
        double var = (dss - ds * ds / n) / (n - 1.0);
        if (var < 0.0) var = 0.0;
        double std = sqrt(var) + 1e-5;
        g_mean[b * NMEL + m] = (float)mean;
        g_rstd[b * NMEL + m] = (float)(1.0 / std);
    }
}

// ---------------------------------------------------------------------------
__global__ __launch_bounds__(256) void out_kernel(
    const int* __restrict__ seq_len, float* __restrict__ out,
    int T, int TP, int extra)
{
    __shared__ float tile[64 * 65];
    __shared__ float mu[64];
    __shared__ float rs[64];

    int b = blockIdx.y;
    int t0 = blockIdx.x * 64;
    int flen = seq_len[b] / HOP + 1;

    if (threadIdx.x < 64) {
        mu[threadIdx.x] = g_mean[b * NMEL + threadIdx.x];
        rs[threadIdx.x] = g_rstd[b * NMEL + threadIdx.x];
    }
    __syncthreads();

    #pragma unroll
    for (int r = 0; r < 16; r++) {
        int idx = r * 256 + threadIdx.x;
        int m = idx & 63;
        int tl = idx >> 6;
        int t = t0 + tl;
        float v = 0.0f;
        if (t < flen) {
            v = (g_logmel[((size_t)(b * T + t)) * NMEL + m] - mu[m]) * rs[m];
        }
        tile[tl * 65 + m] = v;
    }
    __syncthreads();

    #pragma unroll
    for (int r = 0; r < 16; r++) {
        int idx = r * 256 + threadIdx.x;
        int tl = idx & 63;
        int m = idx >> 6;
        int t = t0 + tl;
        if (t < TP) out[((size_t)b * NMEL + m) * TP + t] = tile[tl * 65 + m];
    }

    if (blockIdx.x == 0 && threadIdx.x == 0 && b < extra) {
        size_t tail = (size_t)gridDim.y * NMEL * TP;
        out[tail + b] = (float)flen;
    }
}

// ---------------------------------------------------------------------------
extern "C" void kernel_launch(void* const* d_in, const int* in_sizes, int n_in,
                              void* d_out, int out_size)
{
    const float* x   = (const float*)d_in[0];
    const int*   seq = (const int*)d_in[1];
    const float* win = (const float*)d_in[2];
    const float* fb  = (const float*)d_in[3];
    float* out = (float*)d_out;

    int B = in_sizes[1];
    int L = in_sizes[0] / B;
    int T = L / HOP + 1;
    int TP = ((T + 15) / 16) * 16;

    init_kernel<<<1, 64>>>(fb);

    int nchunk_f = (T + WPB - 1) / WPB;
    frame_kernel<<<B * nchunk_f, 32 * WPB>>>(x, win, fb, L, T, nchunk_f);

    stats_kernel<<<B, 1024>>>(seq, T);

    int nchunk = (TP + 63) / 64;
    long long extra = (long long)out_size - (long long)B * NMEL * TP;
    int ex = extra > 0 ? (int)(extra < B ? extra : B) : 0;
    out_kernel<<<dim3(nchunk, B), 256>>>(seq, out, T, TP, ex);
}